// round 3
// baseline (speedup 1.0000x reference)
#include <cuda_runtime.h>
#include <cuda_bf16.h>
#include <math.h>

// Problem shape (fixed): gramBatch [B=8, C=8, N=1024, 16,16] fp32, out [8,1024,1024] fp32.
// distMat_bc(i,j) = (sq_i + sq_j - 2*dot(i,j)) / (norm_i*norm_j), averaged over c.
//   sq_n   = sum_d g^2
//   norm_n = sqrt(sum_d g^4)
// Symmetric in (i,j): compute only upper-triangular tile pairs and mirror.

#define BB 8
#define CC 8
#define NN 1024
#define DD 256
#define TILE 128
#define KC 32

// Scratch: per-row sq and 1/norm for all (b,c,n) rows. 64K floats each.
__device__ float g_sq[BB * CC * NN];
__device__ float g_rn[BB * CC * NN];

// ---------------------------------------------------------------------------
// Kernel 1: per-row reductions. One warp per row of 256 floats.
// blockDim (32,8), grid = 65536/8 = 8192.
// ---------------------------------------------------------------------------
__global__ void rownorm_kernel(const float* __restrict__ g) {
    int row = blockIdx.x * 8 + threadIdx.y;       // 0 .. 65535
    int lane = threadIdx.x;
    const float* p = g + (size_t)row * DD + lane * 8;
    float4 v0 = *(const float4*)(p + 0);
    float4 v1 = *(const float4*)(p + 4);
    float s2 = 0.f, s4 = 0.f;
    float vals[8] = {v0.x, v0.y, v0.z, v0.w, v1.x, v1.y, v1.z, v1.w};
#pragma unroll
    for (int i = 0; i < 8; ++i) {
        float q = vals[i] * vals[i];
        s2 += q;
        s4 += q * q;
    }
#pragma unroll
    for (int off = 16; off > 0; off >>= 1) {
        s2 += __shfl_xor_sync(0xFFFFFFFFu, s2, off);
        s4 += __shfl_xor_sync(0xFFFFFFFFu, s4, off);
    }
    if (lane == 0) {
        g_sq[row] = s2;
        g_rn[row] = 1.0f / sqrtf(s4);
    }
}

// ---------------------------------------------------------------------------
// Kernel 2: tiled SYRK + fused epilogue + mean over c.
// Grid: (36 triangular tile-pairs, B). Block: 256 threads, 8x8 microtile.
// ---------------------------------------------------------------------------
__global__ __launch_bounds__(256, 1)
void gram_gemm_kernel(const float* __restrict__ g, float* __restrict__ out) {
    __shared__ float As[KC][TILE + 1];
    __shared__ float Bs[KC][TILE + 1];

    // Decode triangular pair index -> (it, jt) with it <= jt.
    int pair = blockIdx.x;
    int it = 0, rem = pair;
    while (rem >= 8 - it) { rem -= 8 - it; ++it; }
    int jt = it + rem;
    int b = blockIdx.y;

    int tid = threadIdx.x;
    int tx = tid & 15;         // j sub-index
    int ty = tid >> 4;         // i sub-index

    float acc[8][8];
#pragma unroll
    for (int ii = 0; ii < 8; ++ii)
#pragma unroll
        for (int jj = 0; jj < 8; ++jj) acc[ii][jj] = 0.f;

    for (int c = 0; c < CC; ++c) {
        const size_t rowA0 = (size_t)(b * CC + c) * NN + it * TILE;
        const size_t rowB0 = (size_t)(b * CC + c) * NN + jt * TILE;
        const float* gA = g + rowA0 * DD;
        const float* gB = g + rowB0 * DD;

        float dot[8][8];
#pragma unroll
        for (int ii = 0; ii < 8; ++ii)
#pragma unroll
            for (int jj = 0; jj < 8; ++jj) dot[ii][jj] = 0.f;

        for (int kt = 0; kt < DD; kt += KC) {
            // Load 128x32 A tile and B tile, transposed into smem.
#pragma unroll
            for (int p = 0; p < 4; ++p) {
                int id = tid + p * 256;       // 0..1023 float4 slots
                int row = id >> 3;            // 0..127
                int c4 = (id & 7) * 4;        // 0,4,...,28
                float4 va = *(const float4*)(gA + (size_t)row * DD + kt + c4);
                As[c4 + 0][row] = va.x;
                As[c4 + 1][row] = va.y;
                As[c4 + 2][row] = va.z;
                As[c4 + 3][row] = va.w;
                float4 vb = *(const float4*)(gB + (size_t)row * DD + kt + c4);
                Bs[c4 + 0][row] = vb.x;
                Bs[c4 + 1][row] = vb.y;
                Bs[c4 + 2][row] = vb.z;
                Bs[c4 + 3][row] = vb.w;
            }
            __syncthreads();

#pragma unroll
            for (int k = 0; k < KC; ++k) {
                float a[8], bv[8];
#pragma unroll
                for (int ii = 0; ii < 8; ++ii) a[ii] = As[k][ii * 16 + ty];
#pragma unroll
                for (int jj = 0; jj < 8; ++jj) bv[jj] = Bs[k][jj * 16 + tx];
#pragma unroll
                for (int ii = 0; ii < 8; ++ii)
#pragma unroll
                    for (int jj = 0; jj < 8; ++jj)
                        dot[ii][jj] += a[ii] * bv[jj];
            }
            __syncthreads();
        }

        // Fused epilogue for this c.
        const float* sqA = g_sq + rowA0;
        const float* rnA = g_rn + rowA0;
        const float* sqB = g_sq + rowB0;
        const float* rnB = g_rn + rowB0;
        float sb[8], rb[8];
#pragma unroll
        for (int jj = 0; jj < 8; ++jj) {
            sb[jj] = sqB[jj * 16 + tx];
            rb[jj] = rnB[jj * 16 + tx];
        }
#pragma unroll
        for (int ii = 0; ii < 8; ++ii) {
            float sa = sqA[ii * 16 + ty];
            float ra = rnA[ii * 16 + ty];
#pragma unroll
            for (int jj = 0; jj < 8; ++jj) {
                acc[ii][jj] += (sa + sb[jj] - 2.0f * dot[ii][jj]) * (ra * rb[jj]);
            }
        }
    }

    // Write out (mean over c), mirroring across the diagonal for it != jt.
    const float scale = 1.0f / (float)CC;
#pragma unroll
    for (int ii = 0; ii < 8; ++ii) {
#pragma unroll
        for (int jj = 0; jj < 8; ++jj) {
            int gi = it * TILE + ii * 16 + ty;
            int gj = jt * TILE + jj * 16 + tx;
            float v = acc[ii][jj] * scale;
            out[((size_t)b << 20) + ((size_t)gi << 10) + gj] = v;
            if (it != jt)
                out[((size_t)b << 20) + ((size_t)gj << 10) + gi] = v;
        }
    }
}

extern "C" void kernel_launch(void* const* d_in, const int* in_sizes, int n_in,
                              void* d_out, int out_size) {
    const float* g = (const float*)d_in[0];
    float* out = (float*)d_out;
    (void)in_sizes; (void)n_in; (void)out_size;

    rownorm_kernel<<<(BB * CC * NN) / 8, dim3(32, 8)>>>(g);
    gram_gemm_kernel<<<dim3(36, BB), 256>>>(g, out);
}

// round 5
// speedup vs baseline: 6.5930x; 6.5930x over previous
#include <cuda_runtime.h>
#include <cuda_bf16.h>
#include <stdint.h>
#include <math.h>

// Problem: gramBatch [B=8, C=8, N=1024, 16,16] fp32 -> out [8,1024,1024] fp32.
// out[b,i,j] = mean_c (sq_i + sq_j - 2*dot_c(i,j)) * rn_i * rn_j,
//   sq = sum_d g^2, rn = 1/sqrt(sum_d g^4).
// GEMM: pre-scale rows by rn (bf16) -> dot' = rn_i*rn_j*dot; accumulate all c
// and K in fp32 registers via mma.sync m16n8k16 bf16 (HMMA; tcgen05 PTX is not
// accepted by this harness's compute_103 virtual arch).
// Additive rank-16 term stays fp32, applied in the epilogue.

#define BB 8
#define CC 8
#define NN 1024
#define DD 256

// bf16 pre-scaled rows, row-major [65536][256]
__device__ __align__(16) unsigned char g_bfb[(size_t)BB * CC * NN * DD * 2];
__device__ float g_u[BB * CC * NN]; // sq * rn
__device__ float g_r[BB * CC * NN]; // rn

// ---------------------------------------------------------------------------
// Prep: per-row reductions + bf16 pre-scaled rows (row-major).
// One warp per row; lane owns 8 consecutive cols.
// ---------------------------------------------------------------------------
__global__ void prep_kernel(const float* __restrict__ g) {
    int row = blockIdx.x * 8 + threadIdx.y;
    int lane = threadIdx.x;
    const float* p = g + (size_t)row * DD + lane * 8;
    float4 v0 = *(const float4*)(p);
    float4 v1 = *(const float4*)(p + 4);
    float vals[8] = {v0.x, v0.y, v0.z, v0.w, v1.x, v1.y, v1.z, v1.w};
    float s2 = 0.f, s4 = 0.f;
#pragma unroll
    for (int i = 0; i < 8; ++i) { float q = vals[i] * vals[i]; s2 += q; s4 += q * q; }
#pragma unroll
    for (int o = 16; o > 0; o >>= 1) {
        s2 += __shfl_xor_sync(0xFFFFFFFFu, s2, o);
        s4 += __shfl_xor_sync(0xFFFFFFFFu, s4, o);
    }
    float rn = 1.0f / sqrtf(s4);
    if (lane == 0) { g_u[row] = s2 * rn; g_r[row] = rn; }

    uint32_t w[4];
#pragma unroll
    for (int q = 0; q < 4; ++q) {
        __nv_bfloat162 h = __floats2bfloat162_rn(vals[2 * q] * rn, vals[2 * q + 1] * rn);
        w[q] = *(uint32_t*)&h;
    }
    *(uint4*)(g_bfb + (size_t)row * 512 + lane * 16) = make_uint4(w[0], w[1], w[2], w[3]);
}

// ---------------------------------------------------------------------------
// Helpers
// ---------------------------------------------------------------------------
__device__ __forceinline__ void ldsm_x4(uint32_t* r, uint32_t a) {
    asm volatile("ldmatrix.sync.aligned.m8n8.x4.shared.b16 {%0,%1,%2,%3}, [%4];"
        : "=r"(r[0]), "=r"(r[1]), "=r"(r[2]), "=r"(r[3]) : "r"(a));
}
__device__ __forceinline__ void mma16816(float* d, const uint32_t* a, uint32_t b0, uint32_t b1) {
    asm volatile("mma.sync.aligned.m16n8k16.row.col.f32.bf16.bf16.f32 "
        "{%0,%1,%2,%3}, {%4,%5,%6,%7}, {%8,%9}, {%0,%1,%2,%3};"
        : "+f"(d[0]), "+f"(d[1]), "+f"(d[2]), "+f"(d[3])
        : "r"(a[0]), "r"(a[1]), "r"(a[2]), "r"(a[3]), "r"(b0), "r"(b1));
}
#define CP_ASYNC(dst, src) \
    asm volatile("cp.async.cg.shared.global [%0], [%1], 16;" :: "r"(dst), "l"(src))
#define CP_COMMIT() asm volatile("cp.async.commit_group;")
#define CP_WAIT1() asm volatile("cp.async.wait_group 1;")
#define CP_WAIT0() asm volatile("cp.async.wait_group 0;")

// ---------------------------------------------------------------------------
// Main: per (tile-pair, b) CTA; 8 warps (2x4), warp tile 64x32.
// 32 chunks (8c x 4 k-chunks of 64), cp.async double buffer.
// ---------------------------------------------------------------------------
__global__ __launch_bounds__(256, 2)
void gram_mma_kernel(float* __restrict__ out) {
    extern __shared__ unsigned char S[];
    uint32_t sbase;
    asm("{ .reg .u64 t; cvta.to.shared.u64 t, %1; cvt.u32.u64 %0, t; }"
        : "=r"(sbase) : "l"(S));

    float2* pA = (float2*)S;                 // [8][128] (u_a, r_a)
    float2* qB = (float2*)(S + 8192);        // [8][128] (r_b, u_b)
    const uint32_t TILES = sbase + 16384;    // 2 stages x (A 16KB + B 16KB)
    float* outT = (float*)(S + 16384);       // reused after GEMM: [128][130]

    int tid = threadIdx.x, lane = tid & 31, wid = tid >> 5;
    int warp_m = wid >> 2, warp_n = wid & 3;
    int pair = blockIdx.x, b = blockIdx.y;
    int it = 0, rem = pair;
    while (rem >= 8 - it) { rem -= 8 - it; ++it; }
    int jt = it + rem;

    // Epilogue scalars into smem.
    for (int idx = tid; idx < 1024; idx += 256) {
        int c = idx >> 7, i = idx & 127;
        int ra = (b * CC + c) * NN + it * 128 + i;
        int rb = (b * CC + c) * NN + jt * 128 + i;
        pA[idx] = make_float2(g_u[ra], g_r[ra]);
        qB[idx] = make_float2(g_r[rb], g_u[rb]);
    }

    // Per-lane cp.async slots: 4 for A, 4 for B.
    int ldr[4], ldq[4];
#pragma unroll
    for (int p = 0; p < 4; ++p) { int id = tid + p * 256; ldr[p] = id >> 3; ldq[p] = id & 7; }

    const size_t rowA0 = (size_t)(b * CC) * NN + it * 128;
    const size_t rowB0 = (size_t)(b * CC) * NN + jt * 128;

    // chunk ch: c = ch>>2, kt = (ch&3)*64 ; gmem byte base offset = row*512 + kt*2
    auto issue = [&](int ch) {
        int c = ch >> 2, kt2 = (ch & 3) * 128; // kt*2 bytes
        uint32_t sA = TILES + (ch & 1) * 32768u;
        uint32_t sB = sA + 16384u;
        const unsigned char* gA = g_bfb + (rowA0 + (size_t)c * NN) * 512 + kt2;
        const unsigned char* gB = g_bfb + (rowB0 + (size_t)c * NN) * 512 + kt2;
#pragma unroll
        for (int p = 0; p < 4; ++p) {
            int r = ldr[p], q = ldq[p];
            uint32_t swz = (uint32_t)(r * 128 + ((q * 16) ^ ((r & 7) * 16)));
            CP_ASYNC(sA + swz, gA + (size_t)r * 512 + q * 16);
            CP_ASYNC(sB + swz, gB + (size_t)r * 512 + q * 16);
        }
        CP_COMMIT();
    };

    // Fragment addressing (per-lane constants).
    int arow = warp_m * 64 + (lane & 15);
    uint32_t aBase = (uint32_t)(arow * 128), aXor = (uint32_t)((arow & 7) * 16);
    uint32_t aKadd = (uint32_t)((lane >> 4) * 16);
    int brow = warp_n * 32 + (lane & 7) + ((lane >> 4) << 3);
    uint32_t bBase = (uint32_t)(brow * 128), bXor = (uint32_t)((brow & 7) * 16);
    uint32_t bKadd = (lane & 8) ? 16u : 0u;

    float acc[4][4][4];
#pragma unroll
    for (int mt = 0; mt < 4; ++mt)
#pragma unroll
        for (int nt = 0; nt < 4; ++nt)
#pragma unroll
            for (int e = 0; e < 4; ++e) acc[mt][nt][e] = 0.f;

    issue(0);
    for (int ch = 0; ch < 32; ++ch) {
        if (ch + 1 < 32) { issue(ch + 1); CP_WAIT1(); }
        else { CP_WAIT0(); }
        __syncthreads();
        uint32_t sA = TILES + (ch & 1) * 32768u;
        uint32_t sB = sA + 16384u;
#pragma unroll
        for (int ks = 0; ks < 4; ++ks) {
            uint32_t kb = (uint32_t)(ks * 32);
            uint32_t afr[4][4], bfr[2][4];
#pragma unroll
            for (int mt = 0; mt < 4; ++mt)
                ldsm_x4(afr[mt], sA + aBase + (uint32_t)(mt * 2048) + ((kb + aKadd) ^ aXor));
#pragma unroll
            for (int n2 = 0; n2 < 2; ++n2)
                ldsm_x4(bfr[n2], sB + bBase + (uint32_t)(n2 * 2048) + ((kb + bKadd) ^ bXor));
#pragma unroll
            for (int mt = 0; mt < 4; ++mt)
#pragma unroll
                for (int nt = 0; nt < 4; ++nt)
                    mma16816(acc[mt][nt], afr[mt], bfr[nt >> 1][(nt & 1) * 2],
                             bfr[nt >> 1][(nt & 1) * 2 + 1]);
        }
        __syncthreads();
    }

    // Stage dot sums into smem (stride 130 floats; float2-aligned).
#pragma unroll
    for (int mt = 0; mt < 4; ++mt) {
        int r1 = warp_m * 64 + mt * 16 + (lane >> 2);
#pragma unroll
        for (int nt = 0; nt < 4; ++nt) {
            int cb = warp_n * 32 + nt * 8 + (lane & 3) * 2;
            *(float2*)&outT[r1 * 130 + cb] = make_float2(acc[mt][nt][0], acc[mt][nt][1]);
            *(float2*)&outT[(r1 + 8) * 130 + cb] = make_float2(acc[mt][nt][2], acc[mt][nt][3]);
        }
    }
    __syncthreads();

    // Correction + direct store. jc is constant per thread -> hoist qB regs.
    int jc = tid & 127;
    unsigned long long qreg[8];
#pragma unroll
    for (int c = 0; c < 8; ++c)
        qreg[c] = *(unsigned long long*)&qB[c * 128 + jc];

    size_t ob = (size_t)b << 20;
    for (int idx = tid; idx < 16384; idx += 256) {
        int r = idx >> 7;
        float dot = outT[r * 130 + jc];
        unsigned long long t = 0ull;
#pragma unroll
        for (int c = 0; c < 8; ++c) {
            unsigned long long pa = *(unsigned long long*)&pA[c * 128 + r];
            asm("fma.rn.f32x2 %0, %1, %2, %0;" : "+l"(t) : "l"(pa), "l"(qreg[c]));
        }
        float2 tf = *(float2*)&t;
        float v = (tf.x + tf.y - 2.0f * dot) * 0.125f;
        out[ob + ((size_t)(it * 128 + r) << 10) + jt * 128 + jc] = v;
        outT[r * 130 + jc] = v;
    }

    if (it != jt) {
        __syncthreads();
        for (int idx = tid; idx < 16384; idx += 256) {
            int rr = idx >> 7, ic = idx & 127;
            out[ob + ((size_t)(jt * 128 + rr) << 10) + it * 128 + ic] = outT[ic * 130 + rr];
        }
    }
}

// ---------------------------------------------------------------------------
extern "C" void kernel_launch(void* const* d_in, const int* in_sizes, int n_in,
                              void* d_out, int out_size) {
    const float* g = (const float*)d_in[0];
    float* out = (float*)d_out;
    (void)in_sizes; (void)n_in; (void)out_size;

    cudaFuncSetAttribute(gram_mma_kernel,
                         cudaFuncAttributeMaxDynamicSharedMemorySize, 83200);

    prep_kernel<<<(BB * CC * NN) / 8, dim3(32, 8)>>>(g);
    gram_mma_kernel<<<dim3(36, BB), 256, 83200>>>(out);
}